// round 5
// baseline (speedup 1.0000x reference)
#include <cuda_runtime.h>

// JointIntegralRegressor: soft-argmax over [16,24,64,64,64] fp32 heatmaps.
// Two plain kernels (fusion via atomics and PDL both measured neutral/worse):
//   pass1: streaming exp-moment reduction, 16 chunks/slice for fine-grained
//          wave scheduling (minimizes last-wave raggedness)
//   pass2: per-slice combine (deterministic fixed order) -> out[slice*3..]

#define DIM_W 64
#define DIM_H 64
#define DIM_D 64
#define SLICES 384                           // 16*24
#define SLICE_ELEMS (DIM_D * DIM_H * DIM_W)  // 262144
#define CHUNKS_PER_SLICE 16
#define CHUNK_ELEMS (SLICE_ELEMS / CHUNKS_PER_SLICE)   // 16384
#define NCHUNKS (SLICES * CHUNKS_PER_SLICE)            // 6144
#define P1_THREADS 256
#define V4_PER_THREAD (CHUNK_ELEMS / 4 / P1_THREADS)   // 16

// Scratch for per-chunk partial moments: (s, sx, sy, sz).
__device__ float4 g_partials[NCHUNKS];

__global__ __launch_bounds__(P1_THREADS)
void jir_pass1(const float* __restrict__ in) {
    const int chunk = blockIdx.x;
    const int tid = threadIdx.x;

    const float4* __restrict__ in4 =
        reinterpret_cast<const float4*>(in) + (long long)chunk * (CHUNK_ELEMS / 4);
    const int elem0 = (chunk & (CHUNKS_PER_SLICE - 1)) * CHUNK_ELEMS;

    float s = 0.f, sx = 0.f, sy = 0.f, sz = 0.f;

    #pragma unroll 4
    for (int it = 0; it < V4_PER_THREAD; ++it) {
        const int idx4 = it * P1_THREADS + tid;     // float4 index in chunk
        const float4 v = __ldcs(&in4[idx4]);        // read-once: evict-first

        const int e  = elem0 + idx4 * 4;            // element index in slice
        const float w0 = (float)(e & (DIM_W - 1));  // x of lane 0 (row-aligned)
        const int   hd = e >> 6;
        const float hf = (float)(hd & (DIM_H - 1));
        const float df = (float)(hd >> 6);

        const float e0 = __expf(v.x);
        const float e1 = __expf(v.y);
        const float e2 = __expf(v.z);
        const float e3 = __expf(v.w);

        const float sp = (e0 + e1) + (e2 + e3);
        // sum_k e_k * (w0 + k) = w0*sp + (e1 + 2*e2 + 3*e3)
        float inner = fmaf(2.f, e2, e1);
        inner       = fmaf(3.f, e3, inner);

        s  += sp;
        sx += fmaf(w0, sp, inner);
        sy  = fmaf(hf, sp, sy);
        sz  = fmaf(df, sp, sz);
    }

    // Block reduction: warp shuffle, then warp-partials through shared memory.
    #pragma unroll
    for (int off = 16; off > 0; off >>= 1) {
        s  += __shfl_down_sync(0xFFFFFFFFu, s,  off);
        sx += __shfl_down_sync(0xFFFFFFFFu, sx, off);
        sy += __shfl_down_sync(0xFFFFFFFFu, sy, off);
        sz += __shfl_down_sync(0xFFFFFFFFu, sz, off);
    }

    __shared__ float4 red[P1_THREADS / 32];
    const int warp = tid >> 5;
    const int lane = tid & 31;
    if (lane == 0) red[warp] = make_float4(s, sx, sy, sz);
    __syncthreads();

    if (tid == 0) {
        float4 acc = red[0];
        #pragma unroll
        for (int i = 1; i < P1_THREADS / 32; ++i) {
            acc.x += red[i].x;
            acc.y += red[i].y;
            acc.z += red[i].z;
            acc.w += red[i].w;
        }
        g_partials[chunk] = acc;
    }
}

__global__ void jir_pass2(float* __restrict__ out) {
    const int slice = blockIdx.x * blockDim.x + threadIdx.x;
    if (slice >= SLICES) return;

    float s = 0.f, sx = 0.f, sy = 0.f, sz = 0.f;
    #pragma unroll
    for (int c = 0; c < CHUNKS_PER_SLICE; ++c) {
        const float4 p = g_partials[slice * CHUNKS_PER_SLICE + c];
        s += p.x; sx += p.y; sy += p.z; sz += p.w;
    }

    const float inv = 1.0f / s;
    const float scale = 1.0f / 64.0f;
    out[slice * 3 + 0] = sx * inv * scale - 0.5f;
    out[slice * 3 + 1] = sy * inv * scale - 0.5f;
    out[slice * 3 + 2] = sz * inv * scale - 0.5f;
}

extern "C" void kernel_launch(void* const* d_in, const int* in_sizes, int n_in,
                              void* d_out, int out_size) {
    const float* heatmaps = (const float*)d_in[0];
    float* out = (float*)d_out;

    jir_pass1<<<NCHUNKS, P1_THREADS>>>(heatmaps);
    jir_pass2<<<3, 128>>>(out);
}

// round 6
// speedup vs baseline: 1.0225x; 1.0225x over previous
#include <cuda_runtime.h>

// JointIntegralRegressor: soft-argmax over [16,24,64,64,64] fp32 heatmaps.
//   pass1: streaming exp-moment reduction (R1 config: 8 chunks/slice,
//          32 float4/thread — best measured MLP/tail tradeoff)
//   pass2: one warp per slice (grid=384) — spreads the partial loads across
//          the chip so they latency-overlap (grid=3 version was DRAM-latency
//          bound at 5.5us).

#define DIM_W 64
#define DIM_H 64
#define DIM_D 64
#define SLICES 384                           // 16*24
#define SLICE_ELEMS (DIM_D * DIM_H * DIM_W)  // 262144
#define CHUNKS_PER_SLICE 8
#define CHUNK_ELEMS (SLICE_ELEMS / CHUNKS_PER_SLICE)   // 32768
#define NCHUNKS (SLICES * CHUNKS_PER_SLICE)            // 3072
#define P1_THREADS 256
#define V4_PER_THREAD (CHUNK_ELEMS / 4 / P1_THREADS)   // 32

// Scratch for per-chunk partial moments: (s, sx, sy, sz).
__device__ float4 g_partials[NCHUNKS];

__global__ __launch_bounds__(P1_THREADS)
void jir_pass1(const float* __restrict__ in) {
    const int chunk = blockIdx.x;
    const int tid = threadIdx.x;

    const float4* __restrict__ in4 =
        reinterpret_cast<const float4*>(in) + (long long)chunk * (CHUNK_ELEMS / 4);
    const int elem0 = (chunk & (CHUNKS_PER_SLICE - 1)) * CHUNK_ELEMS;

    float s = 0.f, sx = 0.f, sy = 0.f, sz = 0.f;

    #pragma unroll 4
    for (int it = 0; it < V4_PER_THREAD; ++it) {
        const int idx4 = it * P1_THREADS + tid;     // float4 index in chunk
        const float4 v = __ldcs(&in4[idx4]);        // read-once: evict-first

        const int e  = elem0 + idx4 * 4;            // element index in slice
        const float w0 = (float)(e & (DIM_W - 1));  // x of lane 0 (row-aligned)
        const int   hd = e >> 6;
        const float hf = (float)(hd & (DIM_H - 1));
        const float df = (float)(hd >> 6);

        const float e0 = __expf(v.x);
        const float e1 = __expf(v.y);
        const float e2 = __expf(v.z);
        const float e3 = __expf(v.w);

        const float sp = (e0 + e1) + (e2 + e3);
        // sum_k e_k * (w0 + k) = w0*sp + (e1 + 2*e2 + 3*e3)
        float inner = fmaf(2.f, e2, e1);
        inner       = fmaf(3.f, e3, inner);

        s  += sp;
        sx += fmaf(w0, sp, inner);
        sy  = fmaf(hf, sp, sy);
        sz  = fmaf(df, sp, sz);
    }

    // Block reduction: warp shuffle, then warp-partials through shared memory.
    #pragma unroll
    for (int off = 16; off > 0; off >>= 1) {
        s  += __shfl_down_sync(0xFFFFFFFFu, s,  off);
        sx += __shfl_down_sync(0xFFFFFFFFu, sx, off);
        sy += __shfl_down_sync(0xFFFFFFFFu, sy, off);
        sz += __shfl_down_sync(0xFFFFFFFFu, sz, off);
    }

    __shared__ float4 red[P1_THREADS / 32];
    const int warp = tid >> 5;
    const int lane = tid & 31;
    if (lane == 0) red[warp] = make_float4(s, sx, sy, sz);
    __syncthreads();

    if (tid == 0) {
        float4 acc = red[0];
        #pragma unroll
        for (int i = 1; i < P1_THREADS / 32; ++i) {
            acc.x += red[i].x;
            acc.y += red[i].y;
            acc.z += red[i].z;
            acc.w += red[i].w;
        }
        g_partials[chunk] = acc;
    }
}

// One 32-thread block per slice. Lanes 0..7 load one partial each, butterfly
// reduce across 8 lanes (fixed order -> deterministic), lane 0 writes.
__global__ __launch_bounds__(32)
void jir_pass2(float* __restrict__ out) {
    const int slice = blockIdx.x;
    const int lane = threadIdx.x;

    float s = 0.f, sx = 0.f, sy = 0.f, sz = 0.f;
    if (lane < CHUNKS_PER_SLICE) {
        const float4 p = g_partials[slice * CHUNKS_PER_SLICE + lane];
        s = p.x; sx = p.y; sy = p.z; sz = p.w;
    }

    #pragma unroll
    for (int off = 4; off > 0; off >>= 1) {
        s  += __shfl_down_sync(0xFFFFFFFFu, s,  off);
        sx += __shfl_down_sync(0xFFFFFFFFu, sx, off);
        sy += __shfl_down_sync(0xFFFFFFFFu, sy, off);
        sz += __shfl_down_sync(0xFFFFFFFFu, sz, off);
    }

    if (lane == 0) {
        const float inv = 1.0f / s;
        const float scale = 1.0f / 64.0f;
        out[slice * 3 + 0] = sx * inv * scale - 0.5f;
        out[slice * 3 + 1] = sy * inv * scale - 0.5f;
        out[slice * 3 + 2] = sz * inv * scale - 0.5f;
    }
}

extern "C" void kernel_launch(void* const* d_in, const int* in_sizes, int n_in,
                              void* d_out, int out_size) {
    const float* heatmaps = (const float*)d_in[0];
    float* out = (float*)d_out;

    jir_pass1<<<NCHUNKS, P1_THREADS>>>(heatmaps);
    jir_pass2<<<SLICES, 32>>>(out);
}